// round 5
// baseline (speedup 1.0000x reference)
#include <cuda_runtime.h>
#include <cuda_bf16.h>
#include <cstdint>

// FusionAVWGCN: out = x@W0(n) + softmax(relu(E E^T))@x @ W1(n) + bias(n)
// B=8, N=8192, Cin=Cout=32, D=16, CHEB_K=2 (supports = [I, A])
// Propagation GEMM runs on tensor cores via legacy mma.sync (bf16, 3-product split).

#define NN 8192
#define BB 8
#define CI 32
#define DD 16

// ---------------- global scratch ----------------
static __device__ __nv_bfloat16 g_xhi[NN * 256];   // [m][bc]
static __device__ __nv_bfloat16 g_xlo[NN * 256];
static __device__ float g_num[2][BB * NN * CI];    // split-K partial numerators
static __device__ float g_den2[2][NN];             // split-K partial denominators

// ---------------- PTX helpers ----------------
__device__ __forceinline__ uint32_t smem_u32(const void* p) {
    uint32_t a;
    asm("{ .reg .u64 t; cvta.to.shared.u64 t, %1; cvt.u32.u64 %0, t; }" : "=r"(a) : "l"(p));
    return a;
}
__device__ __forceinline__ void cp16(void* dst, const void* src) {
    unsigned s = smem_u32(dst);
    asm volatile("cp.async.cg.shared.global [%0], [%1], 16;" :: "r"(s), "l"(src));
}
__device__ __forceinline__ void cp_commit() { asm volatile("cp.async.commit_group;"); }
template <int W> __device__ __forceinline__ void cp_wait() {
    asm volatile("cp.async.wait_group %0;" :: "n"(W));
}
__device__ __forceinline__ unsigned long long pack2(float a) {
    unsigned long long r; asm("mov.b64 %0, {%1, %1};" : "=l"(r) : "f"(a)); return r;
}
__device__ __forceinline__ void fma2(unsigned long long& d, unsigned long long a,
                                     unsigned long long b) {
    asm("fma.rn.f32x2 %0, %1, %2, %0;" : "+l"(d) : "l"(a), "l"(b));
}
__device__ __forceinline__ void unpack2(unsigned long long v, float& lo, float& hi) {
    asm("mov.b64 {%0, %1}, %2;" : "=f"(lo), "=f"(hi) : "l"(v));
}
__device__ __forceinline__ void ldsm4(uint32_t* r, uint32_t addr) {
    asm volatile("ldmatrix.sync.aligned.m8n8.x4.shared.b16 {%0,%1,%2,%3}, [%4];"
                 : "=r"(r[0]), "=r"(r[1]), "=r"(r[2]), "=r"(r[3]) : "r"(addr));
}
__device__ __forceinline__ void ldsm4t(uint32_t* r, uint32_t addr) {
    asm volatile("ldmatrix.sync.aligned.m8n8.x4.trans.shared.b16 {%0,%1,%2,%3}, [%4];"
                 : "=r"(r[0]), "=r"(r[1]), "=r"(r[2]), "=r"(r[3]) : "r"(addr));
}
__device__ __forceinline__ void mma16816(float* d, const uint32_t* a, const uint32_t* b) {
    asm volatile("mma.sync.aligned.m16n8k16.row.col.f32.bf16.bf16.f32 "
                 "{%0,%1,%2,%3}, {%4,%5,%6,%7}, {%8,%9}, {%0,%1,%2,%3};"
                 : "+f"(d[0]), "+f"(d[1]), "+f"(d[2]), "+f"(d[3])
                 : "r"(a[0]), "r"(a[1]), "r"(a[2]), "r"(a[3]), "r"(b[0]), "r"(b[1]));
}
__device__ __forceinline__ uint32_t bpack(float a, float b) {
    __nv_bfloat162 t = __floats2bfloat162_rn(a, b);   // a -> low halfword
    return *(uint32_t*)&t;
}

// ---------------- smem layout (bytes) ----------------
#define XPL    32768                 // one x plane: 64 rows x 512B
#define XBUF   (2 * XPL)             // hi+lo planes
#define OFF_E  131072                // [2 buf][64*16] fp32 = 8192
#define OFF_P  139264                // [2 planes][128 * 144] = 36864
#define PPL    18432
#define SMEM_PROP 176128

// ================= kernel 0: split x into bf16 hi/lo, [m][bc] =================
__global__ void __launch_bounds__(256) splitx_kernel(const float* __restrict__ x) {
    const int id = blockIdx.x * 256 + threadIdx.x;   // 2 elements each
    const int e0 = id * 2;
    const int b = e0 >> 18;            // NN*CI = 262144 per batch
    const int rem = e0 & 262143;
    const int m = rem >> 5, c = rem & 31;
    const float2 v = *(const float2*)(x + e0);
    __nv_bfloat16 h0 = __float2bfloat16(v.x);
    __nv_bfloat16 h1 = __float2bfloat16(v.y);
    float r0 = v.x - __bfloat162float(h0);
    float r1 = v.y - __bfloat162float(h1);
    const int o = m * 256 + b * 32 + c;
    *(uint32_t*)(g_xhi + o) = bpack(__bfloat162float(h0), __bfloat162float(h1));
    *(uint32_t*)(g_xlo + o) = bpack(r0, r1);
}

// ================= kernel 1: mma.sync propagation =================
// y_num[n, bc] = sum_m max(exp(e_n . e_m), 1) * x[m, bc]   (splitK over m halves)
__global__ void __launch_bounds__(256, 1)
prop_kernel(const float* __restrict__ E) {
    extern __shared__ __align__(1024) char smem[];
    const uint32_t sb = smem_u32(smem);
    const int tid = threadIdx.x, lane = tid & 31, w = tid >> 5;
    const int half = blockIdx.x & 1, tile = blockIdx.x >> 1;
    const int mstart = half * 4096;

    // ---- phase A identity: 2 n-rows x 16 m per thread ----
    const int nid = tid >> 2;          // 0..63 -> rows nid, nid+64
    const int qm = tid & 3;            // m quarter
    unsigned long long pea[8], peb[8];
    {
        const float* ea = E + (tile * 128 + nid) * DD;
        const float* eb = E + (tile * 128 + nid + 64) * DD;
#pragma unroll
        for (int k = 0; k < 8; k++) {
            pea[k] = *(const unsigned long long*)(ea + 2 * k);
            peb[k] = *(const unsigned long long*)(eb + 2 * k);
        }
    }

    // ---- MMA identity ----
    const int g = lane >> 3, rr = lane & 7;
    const uint32_t a_off = (uint32_t)((16 * w + (g & 1) * 8 + rr) * 144 + (g >> 1) * 16);
    const uint32_t b_rowb = (uint32_t)((g & 1) * 8 + rr);   // + kk*16
    const uint32_t b_col = (uint32_t)(g >> 1);
    const uint32_t b_xor = (uint32_t)rr;

    float acc[32][4];
#pragma unroll
    for (int j = 0; j < 32; j++)
#pragma unroll
        for (int q = 0; q < 4; q++) acc[j][q] = 0.0f;

    float sa = 0.0f, sbv = 0.0f;

    // ---- loader ----
    auto preload = [&](int c) {
        const int buf = c & 1;
        const int m0 = mstart + c * 64;
#pragma unroll
        for (int pl = 0; pl < 2; pl++) {
            const __nv_bfloat16* src = pl ? g_xlo : g_xhi;
            char* xb = smem + buf * XBUF + pl * XPL;
#pragma unroll
            for (int j = 0; j < 8; j++) {
                int id = tid + j * 256;
                int row = id >> 5, q = id & 31;
                cp16(xb + row * 512 + ((q ^ (row & 7)) << 4),
                     src + (m0 + row) * 256 + q * 8);
            }
        }
        {
            int row = tid >> 2, dq = (tid & 3) << 2;
            float* em = (float*)(smem + OFF_E) + buf * 1024;
            cp16(em + row * DD + dq, E + (m0 + row) * DD + dq);
        }
        cp_commit();
    };

    preload(0);

#pragma unroll 1
    for (int i = 0; i < 64; i++) {
        const int buf = i & 1;
        if (i < 63) { preload(i + 1); cp_wait<1>(); }
        else        { cp_wait<0>(); }
        __syncthreads();

        // ---- phase A: p rows into smem (hi/lo bf16 planes) ----
        {
            const float* em = (float*)(smem + OFF_E) + buf * 1024;
            char* ph = smem + OFF_P;
            char* pl = ph + PPL;
            float pa_prev = 0.f, pb_prev = 0.f;
#pragma unroll
            for (int j = 0; j < 16; j++) {
                const int m = qm * 16 + j;
                const unsigned long long* er = (const unsigned long long*)(em + m * DD);
                unsigned long long da = 0ULL, db = 0ULL;
#pragma unroll
                for (int k = 0; k < 8; k++) {
                    unsigned long long ev = er[k];
                    fma2(da, pea[k], ev);
                    fma2(db, peb[k], ev);
                }
                float lo, hi;
                unpack2(da, lo, hi); float za = lo + hi;
                unpack2(db, lo, hi); float zb = lo + hi;
                float pa = fmaxf(__expf(za), 1.0f);
                float pb = fmaxf(__expf(zb), 1.0f);
                sa += pa; sbv += pb;
                if (j & 1) {
                    // pack pairs (m-1, m)
                    __nv_bfloat16 ha0 = __float2bfloat16(pa_prev);
                    __nv_bfloat16 ha1 = __float2bfloat16(pa);
                    __nv_bfloat16 hb0 = __float2bfloat16(pb_prev);
                    __nv_bfloat16 hb1 = __float2bfloat16(pb);
                    uint32_t oA = (uint32_t)(nid * 144 + (m - 1) * 2);
                    uint32_t oB = (uint32_t)((nid + 64) * 144 + (m - 1) * 2);
                    *(uint32_t*)(ph + oA) = bpack(__bfloat162float(ha0), __bfloat162float(ha1));
                    *(uint32_t*)(ph + oB) = bpack(__bfloat162float(hb0), __bfloat162float(hb1));
                    *(uint32_t*)(pl + oA) = bpack(pa_prev - __bfloat162float(ha0),
                                                  pa - __bfloat162float(ha1));
                    *(uint32_t*)(pl + oB) = bpack(pb_prev - __bfloat162float(hb0),
                                                  pb - __bfloat162float(hb1));
                } else { pa_prev = pa; pb_prev = pb; }
            }
        }
        __syncthreads();

        // ---- MMA: acc += Phi*Xhi + Phi*Xlo + Plo*Xhi ----
        {
            const uint32_t Ph = sb + OFF_P, Pl = Ph + PPL;
            const uint32_t Xh = sb + buf * XBUF, Xl = Xh + XPL;
#pragma unroll
            for (int kk = 0; kk < 4; kk++) {
                uint32_t ah[4], al[4];
                ldsm4(ah, Ph + a_off + kk * 32);
                ldsm4(al, Pl + a_off + kk * 32);
                const uint32_t brow = (b_rowb + kk * 16) * 512;
#pragma unroll
                for (int j = 0; j < 16; j++) {
                    const uint32_t q = 2 * j + b_col;
                    const uint32_t boff = brow + (((q ^ b_xor) & 63) << 4);
                    uint32_t bh[4], bl[4];
                    ldsm4t(bh, Xh + boff);
                    ldsm4t(bl, Xl + boff);
                    mma16816(acc[2 * j],     ah, bh);
                    mma16816(acc[2 * j + 1], ah, bh + 2);
                    mma16816(acc[2 * j],     ah, bl);
                    mma16816(acc[2 * j + 1], ah, bl + 2);
                    mma16816(acc[2 * j],     al, bh);
                    mma16816(acc[2 * j + 1], al, bh + 2);
                }
            }
        }
        __syncthreads();
    }

    // ---- denominators: reduce over 4 m-quarters (quad lanes) ----
    sa += __shfl_xor_sync(0xffffffffu, sa, 1);
    sa += __shfl_xor_sync(0xffffffffu, sa, 2);
    sbv += __shfl_xor_sync(0xffffffffu, sbv, 1);
    sbv += __shfl_xor_sync(0xffffffffu, sbv, 2);
    if (qm == 0) {
        g_den2[half][tile * 128 + nid] = sa;
        g_den2[half][tile * 128 + nid + 64] = sbv;
    }

    // ---- numerator writeout ----
    {
        const int rlo = 16 * w + (lane >> 2);
        const int cpair = (lane & 3) * 2;
        float* base = g_num[half];
#pragma unroll
        for (int jt = 0; jt < 32; jt++) {
            const int bc = jt * 8 + cpair;
            const int b = bc >> 5, c = bc & 31;
            const int n = tile * 128 + rlo;
            *(float2*)(base + (b * NN + n) * CI + c) = make_float2(acc[jt][0], acc[jt][1]);
            *(float2*)(base + (b * NN + n + 8) * CI + c) = make_float2(acc[jt][2], acc[jt][3]);
        }
    }
}

// ================= kernel 2: epilogue =================
// out[b,n,o] = bias[n,o] + sum_i x[b,n,i]*W0[n,i,o] + y[b,n,i]*W1'[n,i,o]
__global__ void __launch_bounds__(256, 1)
epi_kernel(const float* __restrict__ x, const float* __restrict__ E,
           const float* __restrict__ Wp, const float* __restrict__ bp,
           float* __restrict__ out) {
    extern __shared__ float sm[];
    float* sW = sm;               // 32768: layout ((d*32+i)*32+o)*2 + k
    float* sx = sm + 32768;       // [nl][b][i]
    float* sy = sx + 8192;

    const int tid = threadIdx.x;
    const int n0 = blockIdx.x * 32;

#pragma unroll
    for (int jj = 0; jj < 32; jj++) {
        int g4 = tid + jj * 256;
        int gg = g4 * 4;
        float4 v = *(const float4*)(Wp + gg);
        int o0 = gg & 31, ii = (gg >> 5) & 31, k = (gg >> 10) & 1, d = gg >> 11;
        float* dst = sW + ((d * 32 + ii) * 32 + o0) * 2 + k;
        dst[0] = v.x; dst[2] = v.y; dst[4] = v.z; dst[6] = v.w;
    }
#pragma unroll
    for (int k = 0; k < 8; k++) {
        int f4 = tid + k * 256;
        int f = f4 * 4;
        int nl = f >> 8, b = (f >> 5) & 7, i0 = f & 31;
        const int gi = (b * NN + n0 + nl) * CI + i0;
        cp16(sx + f, x + gi);
        float4 y0 = *(const float4*)(g_num[0] + gi);
        float4 y1 = *(const float4*)(g_num[1] + gi);
        *(float4*)(sy + f) = make_float4(y0.x + y1.x, y0.y + y1.y,
                                         y0.z + y1.z, y0.w + y1.w);
    }
    cp_commit();
    cp_wait<0>();
    __syncthreads();

    const int lane = tid & 31;    // output channel o
    const int w = tid >> 5;

#pragma unroll 1
    for (int r = 0; r < 4; r++) {
        const int nl = (r << 3) + w;
        const int n = n0 + nl;

        float e[DD];
#pragma unroll
        for (int d = 0; d < DD; d += 4)
            *(float4*)(e + d) = *(const float4*)(E + n * DD + d);
        unsigned long long pe[DD];
#pragma unroll
        for (int d = 0; d < DD; d++) pe[d] = pack2(e[d]);

        const float invd = 1.0f / (g_den2[0][n] + g_den2[1][n]);

        float bias = 0.0f;
#pragma unroll
        for (int d = 0; d < DD; d++) bias = fmaf(e[d], __ldg(bp + (d << 5) + lane), bias);

        float acc[BB];
#pragma unroll
        for (int b = 0; b < BB; b++) acc[b] = bias;

        const float* xrow = sx + nl * 256;
        const float* yrow = sy + nl * 256;

#pragma unroll 4
        for (int i = 0; i < 32; i++) {
            unsigned long long w01 = 0ULL;
            const float* wp = sW + ((i * 32 + lane) << 1);
#pragma unroll
            for (int d = 0; d < DD; d++)
                fma2(w01, pe[d], *(const unsigned long long*)(wp + (d << 11)));
            float w0, w1;
            unpack2(w01, w0, w1);
            w1 *= invd;
#pragma unroll
            for (int b = 0; b < BB; b++)
                acc[b] = fmaf(xrow[(b << 5) + i], w0, fmaf(yrow[(b << 5) + i], w1, acc[b]));
        }

#pragma unroll
        for (int b = 0; b < BB; b++)
            out[(b * NN + n) * CI + lane] = acc[b];
    }
}

// ---------------- launch ----------------
extern "C" void kernel_launch(void* const* d_in, const int* in_sizes, int n_in,
                              void* d_out, int out_size) {
    const float *x = nullptr, *E = nullptr, *Wp = nullptr, *bp = nullptr;
    for (int i = 0; i < n_in; i++) {
        switch (in_sizes[i]) {
            case BB * NN * CI:     x  = (const float*)d_in[i]; break;
            case NN * DD:          E  = (const float*)d_in[i]; break;
            case DD * 2 * CI * CI: Wp = (const float*)d_in[i]; break;
            case DD * CI:          bp = (const float*)d_in[i]; break;
        }
    }
    cudaFuncSetAttribute(prop_kernel, cudaFuncAttributeMaxDynamicSharedMemorySize, SMEM_PROP);
    cudaFuncSetAttribute(epi_kernel, cudaFuncAttributeMaxDynamicSharedMemorySize,
                         (32768 + 8192 + 8192) * (int)sizeof(float));

    splitx_kernel<<<BB * NN * CI / 512, 256>>>(x);
    prop_kernel<<<128, 256, SMEM_PROP>>>(E);
    epi_kernel<<<NN / 32, 256, (32768 + 8192 + 8192) * sizeof(float)>>>(
        x, E, Wp, bp, (float*)d_out);
}

// round 7
// speedup vs baseline: 1.3275x; 1.3275x over previous
#include <cuda_runtime.h>
#include <cuda_bf16.h>
#include <cstdint>

// FusionAVWGCN: out = x@W0(n) + softmax(relu(E E^T))@x @ W1(n) + bias(n)
// B=8, N=8192, Cin=Cout=32, D=16, CHEB_K=2 (supports = [I, A])
// Propagation GEMM on tensor cores via legacy mma.sync (bf16, 3-product split),
// with warp-private p tiles so phase A overlaps MMA across warps.

#define NN 8192
#define BB 8
#define CI 32
#define DD 16

// ---------------- global scratch ----------------
static __device__ __nv_bfloat16 g_xhi[NN * 256];   // [m][bc]
static __device__ __nv_bfloat16 g_xlo[NN * 256];
static __device__ float g_num[2][BB * NN * CI];    // split-K partial numerators
static __device__ float g_den2[2][NN];             // split-K partial denominators

// ---------------- PTX helpers ----------------
__device__ __forceinline__ uint32_t smem_u32(const void* p) {
    uint32_t a;
    asm("{ .reg .u64 t; cvta.to.shared.u64 t, %1; cvt.u32.u64 %0, t; }" : "=r"(a) : "l"(p));
    return a;
}
__device__ __forceinline__ void cp16(void* dst, const void* src) {
    unsigned s = smem_u32(dst);
    asm volatile("cp.async.cg.shared.global [%0], [%1], 16;" :: "r"(s), "l"(src));
}
__device__ __forceinline__ void cp_commit() { asm volatile("cp.async.commit_group;"); }
template <int W> __device__ __forceinline__ void cp_wait() {
    asm volatile("cp.async.wait_group %0;" :: "n"(W));
}
__device__ __forceinline__ unsigned long long pack2(float a) {
    unsigned long long r; asm("mov.b64 %0, {%1, %1};" : "=l"(r) : "f"(a)); return r;
}
__device__ __forceinline__ void fma2(unsigned long long& d, unsigned long long a,
                                     unsigned long long b) {
    asm("fma.rn.f32x2 %0, %1, %2, %0;" : "+l"(d) : "l"(a), "l"(b));
}
__device__ __forceinline__ void unpack2(unsigned long long v, float& lo, float& hi) {
    asm("mov.b64 {%0, %1}, %2;" : "=f"(lo), "=f"(hi) : "l"(v));
}
__device__ __forceinline__ void ldsm4(uint32_t* r, uint32_t addr) {
    asm volatile("ldmatrix.sync.aligned.m8n8.x4.shared.b16 {%0,%1,%2,%3}, [%4];"
                 : "=r"(r[0]), "=r"(r[1]), "=r"(r[2]), "=r"(r[3]) : "r"(addr));
}
__device__ __forceinline__ void ldsm4t(uint32_t* r, uint32_t addr) {
    asm volatile("ldmatrix.sync.aligned.m8n8.x4.trans.shared.b16 {%0,%1,%2,%3}, [%4];"
                 : "=r"(r[0]), "=r"(r[1]), "=r"(r[2]), "=r"(r[3]) : "r"(addr));
}
__device__ __forceinline__ void mma16816(float* d, const uint32_t* a, const uint32_t* b) {
    asm volatile("mma.sync.aligned.m16n8k16.row.col.f32.bf16.bf16.f32 "
                 "{%0,%1,%2,%3}, {%4,%5,%6,%7}, {%8,%9}, {%0,%1,%2,%3};"
                 : "+f"(d[0]), "+f"(d[1]), "+f"(d[2]), "+f"(d[3])
                 : "r"(a[0]), "r"(a[1]), "r"(a[2]), "r"(a[3]), "r"(b[0]), "r"(b[1]));
}
__device__ __forceinline__ uint32_t bpack(float a, float b) {
    __nv_bfloat162 t = __floats2bfloat162_rn(a, b);   // a -> low halfword
    return *(uint32_t*)&t;
}

// ---------------- smem layout (bytes) ----------------
#define XPL    32768                 // one x plane: 64 rows x 512B
#define XBUF   (2 * XPL)             // hi+lo planes
#define OFF_E  131072                // [2 buf][64*16] fp32 = 8192
#define OFF_P  139264                // [2 planes][128 * 144] = 36864
#define PPL    18432
#define SMEM_PROP 176128

// ================= kernel 0: split x into bf16 hi/lo, [m][bc] =================
__global__ void __launch_bounds__(256) splitx_kernel(const float* __restrict__ x) {
    const int id = blockIdx.x * 256 + threadIdx.x;   // 2 elements each
    const int e0 = id * 2;
    const int b = e0 >> 18;            // NN*CI = 262144 per batch
    const int rem = e0 & 262143;
    const int m = rem >> 5, c = rem & 31;
    const float2 v = *(const float2*)(x + e0);
    __nv_bfloat16 h0 = __float2bfloat16(v.x);
    __nv_bfloat16 h1 = __float2bfloat16(v.y);
    float r0 = v.x - __bfloat162float(h0);
    float r1 = v.y - __bfloat162float(h1);
    const int o = m * 256 + b * 32 + c;
    *(uint32_t*)(g_xhi + o) = bpack(__bfloat162float(h0), __bfloat162float(h1));
    *(uint32_t*)(g_xlo + o) = bpack(r0, r1);
}

// ================= kernel 1: mma.sync propagation =================
// y_num[n, bc] = sum_m max(exp(e_n . e_m), 1) * x[m, bc]   (splitK over m halves)
__global__ void __launch_bounds__(256, 1)
prop_kernel(const float* __restrict__ E) {
    extern __shared__ __align__(1024) char smem[];
    const uint32_t sb = smem_u32(smem);
    const int tid = threadIdx.x, lane = tid & 31, w = tid >> 5;
    const int half = blockIdx.x & 1, tile = blockIdx.x >> 1;
    const int mstart = half * 4096;

    // ---- phase A identity (warp-private rows): lane -> row r of warp w, m-half ----
    const int r = lane >> 1;           // 0..15  (p row 16w + r)
    const int mh = (lane & 1) * 32;    // m offset within 64-chunk
    unsigned long long pe[8];
    {
        const float* er = E + (tile * 128 + 16 * w + r) * DD;
#pragma unroll
        for (int k = 0; k < 8; k++)
            pe[k] = *(const unsigned long long*)(er + 2 * k);
    }
    const uint32_t prow_off = (uint32_t)((16 * w + r) * 144);

    // ---- MMA identity ----
    const int g = lane >> 3, rr = lane & 7;
    const uint32_t a_off = (uint32_t)((16 * w + (g & 1) * 8 + rr) * 144 + (g >> 1) * 16);
    const uint32_t b_rowb = (uint32_t)((g & 1) * 8 + rr);   // + kk*16
    const uint32_t b_col = (uint32_t)(g >> 1);
    const uint32_t b_xor = (uint32_t)rr;

    float acc[32][4];
#pragma unroll
    for (int j = 0; j < 32; j++)
#pragma unroll
        for (int q = 0; q < 4; q++) acc[j][q] = 0.0f;

    float ssum = 0.0f;

    // ---- loader ----
    auto preload = [&](int c) {
        const int buf = c & 1;
        const int m0 = mstart + c * 64;
#pragma unroll
        for (int pl = 0; pl < 2; pl++) {
            const __nv_bfloat16* src = pl ? g_xlo : g_xhi;
            char* xb = smem + buf * XBUF + pl * XPL;
#pragma unroll
            for (int j = 0; j < 8; j++) {
                int id = tid + j * 256;
                int row = id >> 5, q = id & 31;
                cp16(xb + row * 512 + ((q ^ (row & 7)) << 4),
                     src + (m0 + row) * 256 + q * 8);
            }
        }
        {
            int row = tid >> 2, dq = (tid & 3) << 2;
            float* em = (float*)(smem + OFF_E) + buf * 1024;
            cp16(em + row * DD + dq, E + (m0 + row) * DD + dq);
        }
        cp_commit();
    };

    preload(0);

#pragma unroll 1
    for (int i = 0; i < 64; i++) {
        const int buf = i & 1;
        cp_wait<0>();          // x(i) + E(i) landed (had a full iteration in flight)
        __syncthreads();       // all warps done with MMA(i-1); x(i) visible CTA-wide
        if (i < 63) preload(i + 1);

        // ---- phase A (warp-private): p rows 16w..16w+15, hi/lo bf16 planes ----
        {
            const float* em = (float*)(smem + OFF_E) + buf * 1024;
            char* ph = smem + OFF_P;
            char* pl = ph + PPL;
            float prev = 0.0f;
#pragma unroll
            for (int j = 0; j < 32; j++) {
                const int m = mh + j;
                const unsigned long long* er = (const unsigned long long*)(em + m * DD);
                unsigned long long da = 0ULL;
#pragma unroll
                for (int k = 0; k < 8; k++) fma2(da, pe[k], er[k]);
                float lo, hi;
                unpack2(da, lo, hi);
                float pv = fmaxf(__expf(lo + hi), 1.0f);
                ssum += pv;
                if (j & 1) {
                    __nv_bfloat16 h0 = __float2bfloat16(prev);
                    __nv_bfloat16 h1 = __float2bfloat16(pv);
                    const uint32_t off = prow_off + (uint32_t)((m - 1) * 2);
                    *(uint32_t*)(ph + off) = bpack(__bfloat162float(h0), __bfloat162float(h1));
                    *(uint32_t*)(pl + off) = bpack(prev - __bfloat162float(h0),
                                                   pv - __bfloat162float(h1));
                } else prev = pv;
            }
        }
        __syncwarp();          // p tile is intra-warp: producer == consumer warp

        // ---- MMA: acc += Phi*Xhi + Phi*Xlo + Plo*Xhi ----
        {
            const uint32_t Ph = sb + OFF_P, Pl = Ph + PPL;
            const uint32_t Xh = sb + buf * XBUF, Xl = Xh + XPL;
#pragma unroll
            for (int kk = 0; kk < 4; kk++) {
                uint32_t ah[4], al[4];
                ldsm4(ah, Ph + a_off + kk * 32);
                ldsm4(al, Pl + a_off + kk * 32);
                const uint32_t brow = (b_rowb + kk * 16) * 512;
#pragma unroll
                for (int j = 0; j < 16; j++) {
                    const uint32_t q = 2 * j + b_col;
                    const uint32_t boff = brow + (((q ^ b_xor) & 63) << 4);
                    uint32_t bh[4], bl[4];
                    ldsm4t(bh, Xh + boff);
                    ldsm4t(bl, Xl + boff);
                    mma16816(acc[2 * j],     ah, bh);
                    mma16816(acc[2 * j + 1], ah, bh + 2);
                    mma16816(acc[2 * j],     ah, bl);
                    mma16816(acc[2 * j + 1], ah, bl + 2);
                    mma16816(acc[2 * j],     al, bh);
                    mma16816(acc[2 * j + 1], al, bh + 2);
                }
            }
        }
        // no end-of-iter barrier: next-iter __syncthreads provides it
    }

    // ---- denominators: row r of warp w is covered by lane pair (2r, 2r+1) ----
    ssum += __shfl_xor_sync(0xffffffffu, ssum, 1);
    if ((lane & 1) == 0)
        g_den2[half][tile * 128 + 16 * w + r] = ssum;

    // ---- numerator writeout ----
    {
        const int rlo = 16 * w + (lane >> 2);
        const int cpair = (lane & 3) * 2;
        float* base = g_num[half];
#pragma unroll
        for (int jt = 0; jt < 32; jt++) {
            const int bc = jt * 8 + cpair;
            const int b = bc >> 5, c = bc & 31;
            const int n = tile * 128 + rlo;
            *(float2*)(base + (b * NN + n) * CI + c) = make_float2(acc[jt][0], acc[jt][1]);
            *(float2*)(base + (b * NN + n + 8) * CI + c) = make_float2(acc[jt][2], acc[jt][3]);
        }
    }
}

// ================= kernel 2: epilogue =================
// out[b,n,o] = bias[n,o] + sum_i x[b,n,i]*W0[n,i,o] + y[b,n,i]*W1'[n,i,o]
__global__ void __launch_bounds__(256, 1)
epi_kernel(const float* __restrict__ x, const float* __restrict__ E,
           const float* __restrict__ Wp, const float* __restrict__ bp,
           float* __restrict__ out) {
    extern __shared__ float sm[];
    float* sW = sm;               // 32768: layout ((d*32+i)*32+o)*2 + k
    float* sx = sm + 32768;       // [nl][b][i]
    float* sy = sx + 8192;

    const int tid = threadIdx.x;
    const int n0 = blockIdx.x * 32;

#pragma unroll
    for (int jj = 0; jj < 32; jj++) {
        int g4 = tid + jj * 256;
        int gg = g4 * 4;
        float4 v = *(const float4*)(Wp + gg);
        int o0 = gg & 31, ii = (gg >> 5) & 31, k = (gg >> 10) & 1, d = gg >> 11;
        float* dst = sW + ((d * 32 + ii) * 32 + o0) * 2 + k;
        dst[0] = v.x; dst[2] = v.y; dst[4] = v.z; dst[6] = v.w;
    }
#pragma unroll
    for (int k = 0; k < 8; k++) {
        int f4 = tid + k * 256;
        int f = f4 * 4;
        int nl = f >> 8, b = (f >> 5) & 7, i0 = f & 31;
        const int gi = (b * NN + n0 + nl) * CI + i0;
        cp16(sx + f, x + gi);
        float4 y0 = *(const float4*)(g_num[0] + gi);
        float4 y1 = *(const float4*)(g_num[1] + gi);
        *(float4*)(sy + f) = make_float4(y0.x + y1.x, y0.y + y1.y,
                                         y0.z + y1.z, y0.w + y1.w);
    }
    cp_commit();
    cp_wait<0>();
    __syncthreads();

    const int lane = tid & 31;    // output channel o
    const int w = tid >> 5;

#pragma unroll 1
    for (int r = 0; r < 4; r++) {
        const int nl = (r << 3) + w;
        const int n = n0 + nl;

        float e[DD];
#pragma unroll
        for (int d = 0; d < DD; d += 4)
            *(float4*)(e + d) = *(const float4*)(E + n * DD + d);
        unsigned long long pe[DD];
#pragma unroll
        for (int d = 0; d < DD; d++) pe[d] = pack2(e[d]);

        const float invd = 1.0f / (g_den2[0][n] + g_den2[1][n]);

        float bias = 0.0f;
#pragma unroll
        for (int d = 0; d < DD; d++) bias = fmaf(e[d], __ldg(bp + (d << 5) + lane), bias);

        float acc[BB];
#pragma unroll
        for (int b = 0; b < BB; b++) acc[b] = bias;

        const float* xrow = sx + nl * 256;
        const float* yrow = sy + nl * 256;

#pragma unroll 4
        for (int i = 0; i < 32; i++) {
            unsigned long long w01 = 0ULL;
            const float* wp = sW + ((i * 32 + lane) << 1);
#pragma unroll
            for (int d = 0; d < DD; d++)
                fma2(w01, pe[d], *(const unsigned long long*)(wp + (d << 11)));
            float w0, w1;
            unpack2(w01, w0, w1);
            w1 *= invd;
#pragma unroll
            for (int b = 0; b < BB; b++)
                acc[b] = fmaf(xrow[(b << 5) + i], w0, fmaf(yrow[(b << 5) + i], w1, acc[b]));
        }

#pragma unroll
        for (int b = 0; b < BB; b++)
            out[(b * NN + n) * CI + lane] = acc[b];
    }
}

// ---------------- launch ----------------
extern "C" void kernel_launch(void* const* d_in, const int* in_sizes, int n_in,
                              void* d_out, int out_size) {
    const float *x = nullptr, *E = nullptr, *Wp = nullptr, *bp = nullptr;
    for (int i = 0; i < n_in; i++) {
        switch (in_sizes[i]) {
            case BB * NN * CI:     x  = (const float*)d_in[i]; break;
            case NN * DD:          E  = (const float*)d_in[i]; break;
            case DD * 2 * CI * CI: Wp = (const float*)d_in[i]; break;
            case DD * CI:          bp = (const float*)d_in[i]; break;
        }
    }
    cudaFuncSetAttribute(prop_kernel, cudaFuncAttributeMaxDynamicSharedMemorySize, SMEM_PROP);
    cudaFuncSetAttribute(epi_kernel, cudaFuncAttributeMaxDynamicSharedMemorySize,
                         (32768 + 8192 + 8192) * (int)sizeof(float));

    splitx_kernel<<<BB * NN * CI / 512, 256>>>(x);
    prop_kernel<<<128, 256, SMEM_PROP>>>(E);
    epi_kernel<<<NN / 32, 256, (32768 + 8192 + 8192) * sizeof(float)>>>(
        x, E, Wp, bp, (float*)d_out);
}